// round 1
// baseline (speedup 1.0000x reference)
#include <cuda_runtime.h>
#include <math.h>

#define NTOK 384
#define CDIM 128
#define NROWS (NTOK*NTOK)   /* 147456 */
#define EPSV 1e-5f

// Scratch (no cudaMalloc allowed)
__device__ float g_x   [(size_t)NROWS*CDIM];
__device__ float g_left[(size_t)NROWS*CDIM];
__device__ float g_right[(size_t)NROWS*CDIM];
__device__ float g_gate[(size_t)NROWS*CDIM];
__device__ float g_tri [(size_t)NROWS*CDIM];

__device__ __forceinline__ float sigmoidf_(float z){ return 1.f/(1.f+expf(-z)); }

// ---------------- Stage 1: LayerNorm over C ----------------
__global__ __launch_bounds__(128) void ln_kernel(const float* __restrict__ act,
                                                 const float* __restrict__ g,
                                                 const float* __restrict__ b){
  int row = blockIdx.x;
  int c   = threadIdx.x;
  float v = act[(size_t)row*CDIM + c];
  float s = v, s2 = v*v;
  #pragma unroll
  for (int off=16; off>0; off>>=1){
    s  += __shfl_xor_sync(0xffffffffu, s,  off);
    s2 += __shfl_xor_sync(0xffffffffu, s2, off);
  }
  __shared__ float sh[8];
  int wid = c>>5, lane = c&31;
  if (lane==0){ sh[wid]=s; sh[4+wid]=s2; }
  __syncthreads();
  float mu = (sh[0]+sh[1]+sh[2]+sh[3]) * (1.f/CDIM);
  float ms = (sh[4]+sh[5]+sh[6]+sh[7]) * (1.f/CDIM);
  float rs = rsqrtf(ms - mu*mu + EPSV);
  g_x[(size_t)row*CDIM + c] = (v-mu)*rs*g[c] + b[c];
}

// ---------------- shared GEMM tile helper ----------------
// 32 rows x 128 cols output per block, 128 threads.
// thread: tm = tid&31 -> cols {tm, tm+32, tm+64, tm+96}; tr = tid>>5 -> rows tr*8..tr*8+7
__device__ __forceinline__ void gemm_tile(const float* __restrict__ W,
                                          const float* xs, int xstride,
                                          float* ws, int tid, int tm, int tr,
                                          float acc[32]){
  #pragma unroll
  for (int i=0;i<32;i++) acc[i]=0.f;
  for (int ch=0; ch<4; ch++){
    __syncthreads();
    #pragma unroll
    for (int q=0;q<32;q++) ws[q*128+tid] = W[(ch*32+q)*128+tid];
    __syncthreads();
    #pragma unroll
    for (int kk=0;kk<32;kk++){
      float b0 = ws[kk*128+tm];
      float b1 = ws[kk*128+tm+32];
      float b2 = ws[kk*128+tm+64];
      float b3 = ws[kk*128+tm+96];
      int k = ch*32+kk;
      #pragma unroll
      for (int rr=0;rr<8;rr++){
        float a = xs[(tr*8+rr)*xstride + k];
        acc[rr*4+0] = fmaf(a,b0,acc[rr*4+0]);
        acc[rr*4+1] = fmaf(a,b1,acc[rr*4+1]);
        acc[rr*4+2] = fmaf(a,b2,acc[rr*4+2]);
        acc[rr*4+3] = fmaf(a,b3,acc[rr*4+3]);
      }
    }
  }
  __syncthreads();
}

// ---------------- Stage 2: 5 projections + epilogues ----------------
__global__ __launch_bounds__(128) void proj_kernel(const float* __restrict__ mask,
  const float* __restrict__ Wl,  const float* __restrict__ bl,
  const float* __restrict__ Wr,  const float* __restrict__ br,
  const float* __restrict__ Wgl, const float* __restrict__ bgl,
  const float* __restrict__ Wgr, const float* __restrict__ bgr,
  const float* __restrict__ Wg,  const float* __restrict__ bg){
  __shared__ float xs[32*128];
  __shared__ float ws[32*128];
  int tid  = threadIdx.x;
  int row0 = blockIdx.x*32;
  #pragma unroll
  for (int r=0;r<32;r++) xs[r*128+tid] = g_x[(size_t)(row0+r)*CDIM + tid];
  int tm = tid & 31, tr = tid >> 5;
  float acc1[32], acc2[32];

  // left = mask * (x@Wl+bl) * sigmoid(x@Wgl+bgl)
  gemm_tile(Wl,  xs, 128, ws, tid, tm, tr, acc1);
  gemm_tile(Wgl, xs, 128, ws, tid, tm, tr, acc2);
  #pragma unroll
  for (int rr=0;rr<8;rr++){
    int row = row0 + tr*8 + rr;
    float mv = mask[row];
    #pragma unroll
    for (int n=0;n<4;n++){
      int col = tm + 32*n;
      float lin = acc1[rr*4+n] + bl[col];
      float gl  = acc2[rr*4+n] + bgl[col];
      g_left[(size_t)row*CDIM+col] = mv*lin*sigmoidf_(gl);
    }
  }

  // right = mask * (x@Wr+br) * sigmoid(x@Wgr+bgr)
  gemm_tile(Wr,  xs, 128, ws, tid, tm, tr, acc1);
  gemm_tile(Wgr, xs, 128, ws, tid, tm, tr, acc2);
  #pragma unroll
  for (int rr=0;rr<8;rr++){
    int row = row0 + tr*8 + rr;
    float mv = mask[row];
    #pragma unroll
    for (int n=0;n<4;n++){
      int col = tm + 32*n;
      float lin = acc1[rr*4+n] + br[col];
      float gr  = acc2[rr*4+n] + bgr[col];
      g_right[(size_t)row*CDIM+col] = mv*lin*sigmoidf_(gr);
    }
  }

  // gate = sigmoid(x@Wg+bg)
  gemm_tile(Wg, xs, 128, ws, tid, tm, tr, acc1);
  #pragma unroll
  for (int rr=0;rr<8;rr++){
    int row = row0 + tr*8 + rr;
    #pragma unroll
    for (int n=0;n<4;n++){
      int col = tm + 32*n;
      g_gate[(size_t)row*CDIM+col] = sigmoidf_(acc1[rr*4+n] + bg[col]);
    }
  }
}

// ---------------- Stage 3: triangle contraction ----------------
// out[i,j,c] = sum_k L[i,k,c] * R[j,k,c]; thread = channel c, 8x8 (i,j) register tile.
__global__ __launch_bounds__(128) void tri_kernel(){
  int c  = threadIdx.x;
  int i0 = blockIdx.x * 8;
  int j0 = blockIdx.y * 8;
  const float* __restrict__ Lp = g_left  + (size_t)i0*NTOK*CDIM + c;
  const float* __restrict__ Rp = g_right + (size_t)j0*NTOK*CDIM + c;
  float acc[64];
  #pragma unroll
  for (int i=0;i<64;i++) acc[i]=0.f;

  for (int k=0;k<NTOK;k++){
    float a[8], b[8];
    int ko = k*CDIM;
    #pragma unroll
    for (int t=0;t<8;t++) a[t] = Lp[t*(NTOK*CDIM) + ko];
    #pragma unroll
    for (int t=0;t<8;t++) b[t] = Rp[t*(NTOK*CDIM) + ko];
    #pragma unroll
    for (int ii=0;ii<8;ii++)
      #pragma unroll
      for (int jj=0;jj<8;jj++)
        acc[ii*8+jj] = fmaf(a[ii], b[jj], acc[ii*8+jj]);
  }
  #pragma unroll
  for (int ii=0;ii<8;ii++)
    #pragma unroll
    for (int jj=0;jj<8;jj++)
      g_tri[((size_t)(i0+ii)*NTOK + (j0+jj))*CDIM + c] = acc[ii*8+jj];
}

// ---------------- Stage 4: LN(tri) @ Wo + bo, * gate ----------------
__global__ __launch_bounds__(128) void final_kernel(const float* __restrict__ cg,
                                                    const float* __restrict__ cb,
                                                    const float* __restrict__ Wo,
                                                    const float* __restrict__ bo,
                                                    float* __restrict__ out){
  __shared__ float ts[32*129];   // padded rows for conflict-free row scans
  __shared__ float ws[32*128];
  __shared__ float mu_s[32], rs_s[32];
  int tid  = threadIdx.x;
  int row0 = blockIdx.x*32;
  #pragma unroll
  for (int r=0;r<32;r++) ts[r*129+tid] = g_tri[(size_t)(row0+r)*CDIM + tid];
  __syncthreads();
  if (tid < 32){
    float s=0.f, s2=0.f;
    #pragma unroll
    for (int k=0;k<128;k++){ float v = ts[tid*129+k]; s+=v; s2+=v*v; }
    float mu = s*(1.f/128.f);
    mu_s[tid] = mu;
    rs_s[tid] = rsqrtf(s2*(1.f/128.f) - mu*mu + EPSV);
  }
  __syncthreads();
  #pragma unroll
  for (int r=0;r<32;r++)
    ts[r*129+tid] = (ts[r*129+tid]-mu_s[r])*rs_s[r]*cg[tid] + cb[tid];

  int tm = tid&31, tr = tid>>5;
  float acc[32];
  gemm_tile(Wo, ts, 129, ws, tid, tm, tr, acc);
  #pragma unroll
  for (int rr=0;rr<8;rr++){
    int row = row0 + tr*8 + rr;
    #pragma unroll
    for (int n=0;n<4;n++){
      int col = tm + 32*n;
      out[(size_t)row*CDIM+col] = (acc[rr*4+n]+bo[col]) * g_gate[(size_t)row*CDIM+col];
    }
  }
}

extern "C" void kernel_launch(void* const* d_in, const int* in_sizes, int n_in,
                              void* d_out, int out_size) {
  const float* act  = (const float*)d_in[0];
  const float* mask = (const float*)d_in[1];
  const float* ln_g = (const float*)d_in[2];
  const float* ln_b = (const float*)d_in[3];
  const float* Wl   = (const float*)d_in[4];
  const float* bl   = (const float*)d_in[5];
  const float* Wr   = (const float*)d_in[6];
  const float* br   = (const float*)d_in[7];
  const float* Wgl  = (const float*)d_in[8];
  const float* bgl  = (const float*)d_in[9];
  const float* Wgr  = (const float*)d_in[10];
  const float* bgr  = (const float*)d_in[11];
  const float* cg   = (const float*)d_in[12];
  const float* cb   = (const float*)d_in[13];
  const float* Wo   = (const float*)d_in[14];
  const float* bo   = (const float*)d_in[15];
  const float* Wg   = (const float*)d_in[16];
  const float* bg   = (const float*)d_in[17];
  float* out = (float*)d_out;

  ln_kernel<<<NROWS, 128>>>(act, ln_g, ln_b);
  proj_kernel<<<NROWS/32, 128>>>(mask, Wl, bl, Wr, br, Wgl, bgl, Wgr, bgr, Wg, bg);
  tri_kernel<<<dim3(NTOK/8, NTOK/8), 128>>>();
  final_kernel<<<NROWS/32, 128>>>(cg, cb, Wo, bo, out);
}